// round 8
// baseline (speedup 1.0000x reference)
#include <cuda_runtime.h>
#include <cuda_bf16.h>
#include <cstdint>

#define BGR   128          // graphs
#define EPG   4096         // edges per graph
#define ETOT  (BGR*EPG)    // 524288 edges
#define FDIM  128
#define NTMAX (BGR*512)    // 65536 max nodes

// ---------------- device scratch ----------------
__device__ __nv_bfloat16 g_Xa_hi[NTMAX*FDIM];   // aggregated input, split bf16
__device__ __nv_bfloat16 g_Xa_lo[NTMAX*FDIM];
__device__ __nv_bfloat16 g_Wt_hi[FDIM*FDIM];    // W transposed [n][k], split bf16
__device__ __nv_bfloat16 g_Wt_lo[FDIM*FDIM];
__device__ float g_bufB[NTMAX*FDIM];   // H  (post-GEMM features)
__device__ float g_bufC[NTMAX*FDIM];   // xnew (next-stage input)
__device__ float g_s0   [NTMAX];
__device__ int   g_src[ETOT];
__device__ int   g_dst[ETOT];
__device__ unsigned short g_csr_src16[ETOT];    // local src ids (u16)
__device__ float g_csr_w [ETOT];
__device__ int   g_cnt   [NTMAX];
__device__ int   g_off   [NTMAX];
__device__ int   g_newidx[NTMAX];

// =====================================================================
// k_pa: fused per-graph prep (remap+mask+count+dinv+warp-scan+CSR)
//       followed by in-block aggregation Xa -> split bf16 (MLP=8).
// 1024 threads/block; extra block (b == BGR) converts W.
// =====================================================================
template<int NPG, int REMAP, int WRITEBACK>
__global__ __launch_bounds__(1024)
void k_pa(const int* __restrict__ esrc, const int* __restrict__ edst,
          const int* __restrict__ newidx,
          int* __restrict__ osrc, int* __restrict__ odst,
          int* __restrict__ cnt_g, int* __restrict__ off_g,
          unsigned short* __restrict__ csr_src_g, float* __restrict__ csr_w_g,
          const float* __restrict__ X,
          __nv_bfloat16* __restrict__ Xa_hi, __nv_bfloat16* __restrict__ Xa_lo,
          const float* __restrict__ W,
          __nv_bfloat16* __restrict__ Wt_hi, __nv_bfloat16* __restrict__ Wt_lo) {
    const int b = blockIdx.x, t = threadIdx.x;
    if (b == BGR) {
        // transpose + split W[128k][128n] -> Wt[n][k]
#pragma unroll
        for (int it = 0; it < 16; it++) {
            int idx = t + it*1024;
            int n = idx >> 7, k = idx & 127;
            float v = W[k*128 + n];
            __nv_bfloat16 h = __float2bfloat16(v);
            Wt_hi[idx] = h;
            Wt_lo[idx] = __float2bfloat16(v - __bfloat162float(h));
        }
        return;
    }
    __shared__ unsigned short s_src[EPG];   // local src per csr slot
    __shared__ float          s_w  [EPG];
    __shared__ int   s_cnt [NPG];
    __shared__ int   s_cur [NPG];
    __shared__ int   s_offl[NPG];
    __shared__ float s_dinv[NPG];
    __shared__ int   s_ws  [NPG/32];        // warp partial sums
    const int ebase = b * EPG;
    const int nbase = b * NPG;
    const int lane = t & 31, wid = t >> 5;
    if (t < NPG) s_cnt[t] = 0;
    __syncthreads();

    int ls[4], ldst[4];
#pragma unroll
    for (int u = 0; u < 4; u++) {
        int e = ebase + u*1024 + t;
        int s = esrc[e], d = edst[e];
        if (REMAP) {
            if (d >= 0) {
                int ns = newidx[s], nd = newidx[d];
                if (ns < 0 || nd < 0) d = -1;
                else { s = ns; d = nd; }
            }
        }
        if (WRITEBACK) { osrc[e] = s; odst[e] = d; }
        if (d >= 0) {
            ls[u]   = s - nbase;
            ldst[u] = d - nbase;
            atomicAdd(&s_cnt[ldst[u]], 1);
        } else ldst[u] = -1;
    }
    __syncthreads();

    // ---- two-level warp-shuffle exclusive scan over NPG counts ----
    int c = 0, vincl = 0;
    if (t < NPG) {
        c = s_cnt[t];
        vincl = c;
#pragma unroll
        for (int d = 1; d < 32; d <<= 1) {
            int nv = __shfl_up_sync(0xFFFFFFFFu, vincl, d);
            if (lane >= d) vincl += nv;
        }
        if (lane == 31) s_ws[wid] = vincl;
        cnt_g[nbase + t] = c;
        s_dinv[t] = rsqrtf((float)c + 1.f);
    }
    __syncthreads();
    if (t < 32) {
        constexpr int NW = NPG/32;
        int v = (t < NW) ? s_ws[t] : 0;
#pragma unroll
        for (int d = 1; d < 32; d <<= 1) {
            int nv = __shfl_up_sync(0xFFFFFFFFu, v, d);
            if (lane >= d) v += nv;
        }
        if (t < NW) s_ws[t] = v;        // inclusive warp-sum prefix
    }
    __syncthreads();
    if (t < NPG) {
        int base = (wid > 0) ? s_ws[wid - 1] : 0;
        int excl = base + vincl - c;
        off_g[nbase + t] = ebase + excl;
        s_offl[t] = excl;
        s_cur[t]  = excl;
    }
    __syncthreads();

#pragma unroll
    for (int u = 0; u < 4; u++) {
        if (ldst[u] >= 0) {
            int pos = atomicAdd(&s_cur[ldst[u]], 1);
            float w = s_dinv[ls[u]] * s_dinv[ldst[u]];
            s_src[pos] = (unsigned short)ls[u];
            s_w  [pos] = w;
            csr_src_g[ebase + pos] = (unsigned short)ls[u];
            csr_w_g  [ebase + pos] = w;
        }
    }
    __syncthreads();

    // ------------- aggregation (32 warps over NPG nodes, MLP=8) -----
    for (int node = wid; node < NPG; node += 32) {
        int cc = s_cnt[node], o = s_offl[node];
        float self = 1.f / ((float)cc + 1.f);
        size_t gi = (size_t)(nbase + node)*128 + lane*4;
        float4 hv = *(const float4*)(X + gi);
        float4 a0 = make_float4(self*hv.x, self*hv.y, self*hv.z, self*hv.w);
        float4 a1 = make_float4(0,0,0,0), a2 = make_float4(0,0,0,0), a3 = make_float4(0,0,0,0);
        float4 a4 = make_float4(0,0,0,0), a5 = make_float4(0,0,0,0);
        float4 a6 = make_float4(0,0,0,0), a7 = make_float4(0,0,0,0);
        int j = 0;
        for (; j + 8 <= cc; j += 8) {
            int   n0 = s_src[o+j],   n1 = s_src[o+j+1];
            int   n2 = s_src[o+j+2], n3 = s_src[o+j+3];
            int   n4 = s_src[o+j+4], n5 = s_src[o+j+5];
            int   n6 = s_src[o+j+6], n7 = s_src[o+j+7];
            float w0 = s_w[o+j],   w1 = s_w[o+j+1];
            float w2 = s_w[o+j+2], w3 = s_w[o+j+3];
            float w4 = s_w[o+j+4], w5 = s_w[o+j+5];
            float w6 = s_w[o+j+6], w7 = s_w[o+j+7];
            float4 h0 = *(const float4*)(X + (size_t)(nbase+n0)*128 + lane*4);
            float4 h1 = *(const float4*)(X + (size_t)(nbase+n1)*128 + lane*4);
            float4 h2 = *(const float4*)(X + (size_t)(nbase+n2)*128 + lane*4);
            float4 h3 = *(const float4*)(X + (size_t)(nbase+n3)*128 + lane*4);
            float4 h4 = *(const float4*)(X + (size_t)(nbase+n4)*128 + lane*4);
            float4 h5 = *(const float4*)(X + (size_t)(nbase+n5)*128 + lane*4);
            float4 h6 = *(const float4*)(X + (size_t)(nbase+n6)*128 + lane*4);
            float4 h7 = *(const float4*)(X + (size_t)(nbase+n7)*128 + lane*4);
            a0.x += w0*h0.x; a0.y += w0*h0.y; a0.z += w0*h0.z; a0.w += w0*h0.w;
            a1.x += w1*h1.x; a1.y += w1*h1.y; a1.z += w1*h1.z; a1.w += w1*h1.w;
            a2.x += w2*h2.x; a2.y += w2*h2.y; a2.z += w2*h2.z; a2.w += w2*h2.w;
            a3.x += w3*h3.x; a3.y += w3*h3.y; a3.z += w3*h3.z; a3.w += w3*h3.w;
            a4.x += w4*h4.x; a4.y += w4*h4.y; a4.z += w4*h4.z; a4.w += w4*h4.w;
            a5.x += w5*h5.x; a5.y += w5*h5.y; a5.z += w5*h5.z; a5.w += w5*h5.w;
            a6.x += w6*h6.x; a6.y += w6*h6.y; a6.z += w6*h6.z; a6.w += w6*h6.w;
            a7.x += w7*h7.x; a7.y += w7*h7.y; a7.z += w7*h7.z; a7.w += w7*h7.w;
        }
        for (; j + 4 <= cc; j += 4) {
            int   n0 = s_src[o+j],   n1 = s_src[o+j+1];
            int   n2 = s_src[o+j+2], n3 = s_src[o+j+3];
            float w0 = s_w[o+j],   w1 = s_w[o+j+1];
            float w2 = s_w[o+j+2], w3 = s_w[o+j+3];
            float4 h0 = *(const float4*)(X + (size_t)(nbase+n0)*128 + lane*4);
            float4 h1 = *(const float4*)(X + (size_t)(nbase+n1)*128 + lane*4);
            float4 h2 = *(const float4*)(X + (size_t)(nbase+n2)*128 + lane*4);
            float4 h3 = *(const float4*)(X + (size_t)(nbase+n3)*128 + lane*4);
            a0.x += w0*h0.x; a0.y += w0*h0.y; a0.z += w0*h0.z; a0.w += w0*h0.w;
            a1.x += w1*h1.x; a1.y += w1*h1.y; a1.z += w1*h1.z; a1.w += w1*h1.w;
            a2.x += w2*h2.x; a2.y += w2*h2.y; a2.z += w2*h2.z; a2.w += w2*h2.w;
            a3.x += w3*h3.x; a3.y += w3*h3.y; a3.z += w3*h3.z; a3.w += w3*h3.w;
        }
        for (; j < cc; j++) {
            int s = s_src[o+j]; float w = s_w[o+j];
            float4 hs = *(const float4*)(X + (size_t)(nbase+s)*128 + lane*4);
            a0.x += w*hs.x; a0.y += w*hs.y; a0.z += w*hs.z; a0.w += w*hs.w;
        }
        a0.x += (a1.x + a2.x) + (a3.x + a4.x) + (a5.x + a6.x) + a7.x;
        a0.y += (a1.y + a2.y) + (a3.y + a4.y) + (a5.y + a6.y) + a7.y;
        a0.z += (a1.z + a2.z) + (a3.z + a4.z) + (a5.z + a6.z) + a7.z;
        a0.w += (a1.w + a2.w) + (a3.w + a4.w) + (a5.w + a6.w) + a7.w;
        float f[4] = {a0.x, a0.y, a0.z, a0.w};
        __nv_bfloat16 hi4[4], lo4[4];
#pragma unroll
        for (int e = 0; e < 4; e++) {
            hi4[e] = __float2bfloat16(f[e]);
            lo4[e] = __float2bfloat16(f[e] - __bfloat162float(hi4[e]));
        }
        *(uint2*)(Xa_hi + gi) = *(uint2*)hi4;
        *(uint2*)(Xa_lo + gi) = *(uint2*)lo4;
    }
}

// =====================================================================
// Tensor-core GEMM (split-bf16 operands preconverted; 3 MMA terms):
//   H[M,128] = relu(Xa @ W + b); epilogue also computes s0 = H.Ws
// =====================================================================
__device__ __forceinline__ void mma_bf16(float* d, const unsigned* a, const unsigned* b) {
    asm volatile(
        "mma.sync.aligned.m16n8k16.row.col.f32.bf16.bf16.f32 "
        "{%0,%1,%2,%3}, {%4,%5,%6,%7}, {%8,%9}, {%0,%1,%2,%3};\n"
        : "+f"(d[0]), "+f"(d[1]), "+f"(d[2]), "+f"(d[3])
        : "r"(a[0]), "r"(a[1]), "r"(a[2]), "r"(a[3]), "r"(b[0]), "r"(b[1]));
}

__global__ __launch_bounds__(256)
void k_gemm_tc(const __nv_bfloat16* __restrict__ A_hi,
               const __nv_bfloat16* __restrict__ A_lo,
               const __nv_bfloat16* __restrict__ Wt_hi,
               const __nv_bfloat16* __restrict__ Wt_lo,
               const float* __restrict__ bias, const float* __restrict__ Ws,
               float* __restrict__ C, float* __restrict__ s0) {
    __shared__ __align__(16) __nv_bfloat16 As_hi[128][40];
    __shared__ __align__(16) __nv_bfloat16 As_lo[128][40];
    __shared__ __align__(16) __nv_bfloat16 Bt_hi[128][40];
    __shared__ __align__(16) __nv_bfloat16 Bt_lo[128][40];
    __shared__ float s0part[2][128];

    const int t = threadIdx.x;
    const int warp = t >> 5, lane = t & 31;
    const int warpM = warp >> 1, warpN = warp & 1;
    const int row0 = blockIdx.x * 128;
    const int lq = lane >> 2;
    const int lr = lane & 3;

    float acc[2][8][4];
#pragma unroll
    for (int mt = 0; mt < 2; mt++)
#pragma unroll
        for (int nt = 0; nt < 8; nt++)
#pragma unroll
            for (int r = 0; r < 4; r++) acc[mt][nt][r] = 0.f;

    for (int kc = 0; kc < 4; kc++) {
#pragma unroll
        for (int it = 0; it < 2; it++) {
            int idx = t + it*256;
            int row = idx >> 2;
            int kq  = (idx & 3) * 8;
            size_t ga = (size_t)(row0 + row)*128 + kc*32 + kq;
            *(uint4*)&As_hi[row][kq] = *(const uint4*)(A_hi + ga);
            *(uint4*)&As_lo[row][kq] = *(const uint4*)(A_lo + ga);
            size_t gb = (size_t)row*128 + kc*32 + kq;
            *(uint4*)&Bt_hi[row][kq] = *(const uint4*)(Wt_hi + gb);
            *(uint4*)&Bt_lo[row][kq] = *(const uint4*)(Wt_lo + gb);
        }
        __syncthreads();

#pragma unroll
        for (int ks = 0; ks < 2; ks++) {
            const int kb = ks * 16;
            unsigned a_hi[2][4], a_lo[2][4], b_hi[8][2], b_lo[8][2];
#pragma unroll
            for (int mt = 0; mt < 2; mt++) {
                int m = warpM*32 + mt*16 + lq;
                a_hi[mt][0] = *(const unsigned*)&As_hi[m    ][kb + 2*lr];
                a_hi[mt][1] = *(const unsigned*)&As_hi[m + 8][kb + 2*lr];
                a_hi[mt][2] = *(const unsigned*)&As_hi[m    ][kb + 2*lr + 8];
                a_hi[mt][3] = *(const unsigned*)&As_hi[m + 8][kb + 2*lr + 8];
                a_lo[mt][0] = *(const unsigned*)&As_lo[m    ][kb + 2*lr];
                a_lo[mt][1] = *(const unsigned*)&As_lo[m + 8][kb + 2*lr];
                a_lo[mt][2] = *(const unsigned*)&As_lo[m    ][kb + 2*lr + 8];
                a_lo[mt][3] = *(const unsigned*)&As_lo[m + 8][kb + 2*lr + 8];
            }
#pragma unroll
            for (int nt = 0; nt < 8; nt++) {
                int n = warpN*64 + nt*8 + lq;
                b_hi[nt][0] = *(const unsigned*)&Bt_hi[n][kb + 2*lr];
                b_hi[nt][1] = *(const unsigned*)&Bt_hi[n][kb + 2*lr + 8];
                b_lo[nt][0] = *(const unsigned*)&Bt_lo[n][kb + 2*lr];
                b_lo[nt][1] = *(const unsigned*)&Bt_lo[n][kb + 2*lr + 8];
            }
#pragma unroll
            for (int mt = 0; mt < 2; mt++)
#pragma unroll
                for (int nt = 0; nt < 8; nt++) {
                    mma_bf16(acc[mt][nt], a_hi[mt], b_hi[nt]);
                    mma_bf16(acc[mt][nt], a_lo[mt], b_hi[nt]);
                    mma_bf16(acc[mt][nt], a_hi[mt], b_lo[nt]);
                }
        }
        __syncthreads();
    }

    float pacc[2][2] = {{0.f,0.f},{0.f,0.f}};
#pragma unroll
    for (int nt = 0; nt < 8; nt++) {
        int n0 = warpN*64 + nt*8 + 2*lr;
        float bb0 = __ldg(bias + n0), bb1 = __ldg(bias + n0 + 1);
        float ww0 = __ldg(Ws + n0),   ww1 = __ldg(Ws + n0 + 1);
#pragma unroll
        for (int mt = 0; mt < 2; mt++) {
            int r0 = warpM*32 + mt*16 + lq;
            float v0 = fmaxf(acc[mt][nt][0] + bb0, 0.f);
            float v1 = fmaxf(acc[mt][nt][1] + bb1, 0.f);
            float v2 = fmaxf(acc[mt][nt][2] + bb0, 0.f);
            float v3 = fmaxf(acc[mt][nt][3] + bb1, 0.f);
            *(float2*)(C + (size_t)(row0 + r0)*128 + n0)     = make_float2(v0, v1);
            *(float2*)(C + (size_t)(row0 + r0 + 8)*128 + n0) = make_float2(v2, v3);
            pacc[mt][0] += v0*ww0 + v1*ww1;
            pacc[mt][1] += v2*ww0 + v3*ww1;
        }
    }
#pragma unroll
    for (int mt = 0; mt < 2; mt++)
#pragma unroll
        for (int h = 0; h < 2; h++) {
            float p = pacc[mt][h];
            p += __shfl_xor_sync(0xFFFFFFFFu, p, 1);
            p += __shfl_xor_sync(0xFFFFFFFFu, p, 2);
            if (lr == 0) s0part[warpN][warpM*32 + mt*16 + lq + h*8] = p;
        }
    __syncthreads();
    if (t < 128) s0[row0 + t] = s0part[0][t] + s0part[1][t];
}

// =====================================================================
// k_txr: fused score-GCN (MLP=8) + hybrid bitonic top-k + gather*tanh + readout
// =====================================================================
template<int NPG, int ACCUM>
__global__ void k_txr(const int* __restrict__ cnt, const int* __restrict__ off,
                      const unsigned short* __restrict__ csr_src,
                      const float* __restrict__ csr_w,
                      const float* __restrict__ s0, const float* __restrict__ bs,
                      int* __restrict__ newidx,
                      const float* __restrict__ H, float* __restrict__ xnew,
                      float* __restrict__ out) {
    constexpr int K = NPG/2;
    constexpr int G = NPG/128;           // readout row-groups
    __shared__ unsigned long long keys[NPG];
    __shared__ float s_s0l[NPG];
    __shared__ float s_sc [NPG];
    __shared__ int   s_old[K];
    __shared__ float s_t  [K];
    __shared__ float r_mx [NPG];
    __shared__ float r_sm [NPG];
    const int b = blockIdx.x, i = threadIdx.x;
    const int nbase = b*NPG;
    const int gi = nbase + i;

    // ---- score GCN (s0 staged in smem, MLP=8) ----
    s_s0l[i] = s0[gi];
    __syncthreads();
    int c = cnt[gi], o = off[gi];
    float acc = bs[0] + s_s0l[i] / ((float)c + 1.f);
    float acc1 = 0.f, acc2 = 0.f, acc3 = 0.f;
    float acc4 = 0.f, acc5 = 0.f, acc6 = 0.f, acc7 = 0.f;
    int j = 0;
    for (; j + 8 <= c; j += 8) {
        int   n0 = csr_src[o+j],   n1 = csr_src[o+j+1];
        int   n2 = csr_src[o+j+2], n3 = csr_src[o+j+3];
        int   n4 = csr_src[o+j+4], n5 = csr_src[o+j+5];
        int   n6 = csr_src[o+j+6], n7 = csr_src[o+j+7];
        float w0 = csr_w[o+j],   w1 = csr_w[o+j+1];
        float w2 = csr_w[o+j+2], w3 = csr_w[o+j+3];
        float w4 = csr_w[o+j+4], w5 = csr_w[o+j+5];
        float w6 = csr_w[o+j+6], w7 = csr_w[o+j+7];
        acc  += w0 * s_s0l[n0];
        acc1 += w1 * s_s0l[n1];
        acc2 += w2 * s_s0l[n2];
        acc3 += w3 * s_s0l[n3];
        acc4 += w4 * s_s0l[n4];
        acc5 += w5 * s_s0l[n5];
        acc6 += w6 * s_s0l[n6];
        acc7 += w7 * s_s0l[n7];
    }
    for (; j + 4 <= c; j += 4) {
        int   n0 = csr_src[o+j],   n1 = csr_src[o+j+1];
        int   n2 = csr_src[o+j+2], n3 = csr_src[o+j+3];
        float w0 = csr_w[o+j],   w1 = csr_w[o+j+1];
        float w2 = csr_w[o+j+2], w3 = csr_w[o+j+3];
        acc  += w0 * s_s0l[n0];
        acc1 += w1 * s_s0l[n1];
        acc2 += w2 * s_s0l[n2];
        acc3 += w3 * s_s0l[n3];
    }
    for (; j < c; j++) acc += csr_w[o+j] * s_s0l[csr_src[o+j]];
    acc += (acc1 + acc2) + (acc3 + acc4) + (acc5 + acc6) + acc7;
    s_sc[i] = acc;
    unsigned u  = __float_as_uint(acc);
    unsigned ou = u ^ ((u & 0x80000000u) ? 0xFFFFFFFFu : 0x80000000u);
    keys[i] = ((unsigned long long)(~ou) << 32) | (unsigned)i;  // asc => desc score, asc idx
    __syncthreads();

    // ---- hybrid bitonic sort: smem steps for j>=32, shfl for j<32 ----
    for (int kk = 2; kk <= NPG; kk <<= 1) {
        for (int js = kk >> 1; js >= 32; js >>= 1) {
            int ixj = i ^ js;
            if (ixj > i) {
                bool up = ((i & kk) == 0);
                unsigned long long a = keys[i], cc2 = keys[ixj];
                if ((a > cc2) == up) { keys[i] = cc2; keys[ixj] = a; }
            }
            __syncthreads();
        }
        {
            unsigned long long v = keys[i];
            const bool up = ((i & kk) == 0);
            int js0 = (kk >> 1) < 16 ? (kk >> 1) : 16;
            for (int js = js0; js > 0; js >>= 1) {
                unsigned long long p = __shfl_xor_sync(0xFFFFFFFFu, v, js);
                bool keepSmall = (((i & js) == 0) == up);
                if ((p < v) == keepSmall) v = p;
            }
            keys[i] = v;
        }
        __syncthreads();
    }

    // ---- topk outputs + newidx ----
    int idx = (int)(keys[i] & 0xFFFFFFFFull);
    if (i < K) {
        s_old[i] = idx;
        s_t[i]   = tanhf(s_sc[idx]);
        newidx[nbase + idx] = b*K + i;
    } else {
        newidx[nbase + idx] = -1;
    }
    __syncthreads();

    // ---- gather*tanh + readout (G row-groups of 128 columns) ----
    const int col = i & 127, g = i >> 7;
    float mx = -3.402823466e38f, sm = 0.f;
    for (int jr = g; jr < K; jr += G) {
        float v = H[(size_t)(nbase + s_old[jr])*128 + col] * s_t[jr];
        xnew[(size_t)(b*K + jr)*128 + col] = v;
        mx = fmaxf(mx, v); sm += v;
    }
    if (G > 1) {
        r_mx[g*128 + col] = mx;
        r_sm[g*128 + col] = sm;
        __syncthreads();
        if (g == 0) {
#pragma unroll
            for (int gg = 1; gg < G; gg++) {
                mx = fmaxf(mx, r_mx[gg*128 + col]);
                sm += r_sm[gg*128 + col];
            }
        }
    }
    if (g == 0) {
        if (ACCUM) {
            out[b*256 + col]       += mx;
            out[b*256 + 128 + col] += sm / (float)K;
        } else {
            out[b*256 + col]       = mx;
            out[b*256 + 128 + col] = sm / (float)K;
        }
    }
}

// =====================================================================
extern "C" void kernel_launch(void* const* d_in, const int* in_sizes, int n_in,
                              void* d_out, int out_size) {
    const float* x   = (const float*)d_in[0];
    const int*   ei  = (const int*)  d_in[1];
    const float* W1  = (const float*)d_in[3];
    const float* b1  = (const float*)d_in[4];
    const float* Ws1 = (const float*)d_in[5];
    const float* bs1 = (const float*)d_in[6];
    const float* W2  = (const float*)d_in[7];
    const float* b2  = (const float*)d_in[8];
    const float* Ws2 = (const float*)d_in[9];
    const float* bs2 = (const float*)d_in[10];
    const float* W3  = (const float*)d_in[11];
    const float* b3  = (const float*)d_in[12];
    const float* Ws3 = (const float*)d_in[13];
    const float* bs3 = (const float*)d_in[14];
    float* out = (float*)d_out;

    __nv_bfloat16 *xah, *xal, *wth, *wtl;
    float *bufB, *bufC, *s0p, *csrw;
    unsigned short *csrs;
    int *srcp, *dstp, *cntp, *offp, *newip;
    cudaGetSymbolAddress((void**)&xah,   g_Xa_hi);
    cudaGetSymbolAddress((void**)&xal,   g_Xa_lo);
    cudaGetSymbolAddress((void**)&wth,   g_Wt_hi);
    cudaGetSymbolAddress((void**)&wtl,   g_Wt_lo);
    cudaGetSymbolAddress((void**)&bufB,  g_bufB);
    cudaGetSymbolAddress((void**)&bufC,  g_bufC);
    cudaGetSymbolAddress((void**)&s0p,   g_s0);
    cudaGetSymbolAddress((void**)&csrw,  g_csr_w);
    cudaGetSymbolAddress((void**)&srcp,  g_src);
    cudaGetSymbolAddress((void**)&dstp,  g_dst);
    cudaGetSymbolAddress((void**)&csrs,  g_csr_src16);
    cudaGetSymbolAddress((void**)&cntp,  g_cnt);
    cudaGetSymbolAddress((void**)&offp,  g_off);
    cudaGetSymbolAddress((void**)&newip, g_newidx);

    const int* ei_src = ei;
    const int* ei_dst = ei + ETOT;

    // ---------------- stage 1: n=512, k=256 ----------------
    {
        const int NT = BGR*512;
        k_pa<512,0,0><<<BGR+1,1024>>>(ei_src, ei_dst, newip, srcp, dstp,
                                      cntp, offp, csrs, csrw,
                                      x, xah, xal, W1, wth, wtl);
        k_gemm_tc<<<NT/128,256>>>(xah, xal, wth, wtl, b1, Ws1, bufB, s0p);
        k_txr<512,0><<<BGR,512>>>(cntp, offp, csrs, csrw, s0p, bs1, newip,
                                  bufB, bufC, out);
    }
    // ---------------- stage 2: n=256, k=128 ----------------
    {
        const int NT = BGR*256;
        k_pa<256,1,1><<<BGR+1,1024>>>(ei_src, ei_dst, newip, srcp, dstp,
                                      cntp, offp, csrs, csrw,
                                      bufC, xah, xal, W2, wth, wtl);
        k_gemm_tc<<<NT/128,256>>>(xah, xal, wth, wtl, b2, Ws2, bufB, s0p);
        k_txr<256,1><<<BGR,256>>>(cntp, offp, csrs, csrw, s0p, bs2, newip,
                                  bufB, bufC, out);
    }
    // ---------------- stage 3: n=128, k=64 ----------------
    {
        const int NT = BGR*128;
        k_pa<128,1,0><<<BGR+1,1024>>>(srcp, dstp, newip, srcp, dstp,
                                      cntp, offp, csrs, csrw,
                                      bufC, xah, xal, W3, wth, wtl);
        k_gemm_tc<<<NT/128,256>>>(xah, xal, wth, wtl, b3, Ws3, bufB, s0p);
        k_txr<128,1><<<BGR,128>>>(cntp, offp, csrs, csrw, s0p, bs3, newip,
                                  bufB, bufC, out);
    }
}